// round 15
// baseline (speedup 1.0000x reference)
#include <cuda_runtime.h>
#include <cuda_fp16.h>
#include <math.h>
#include <stdint.h>

#define Bv   8
#define Nv   8192
#define Cv   64
#define Pv   2048
#define Kv   16
#define H1v  64
#define H2v  128
#define EPSv 1e-5f

// ---- smem byte offsets for mlp kernel (OB overlaid into A1 tail) ----
#define W1_OFF   0          // [64][88] f16   = 11264 B
#define W2_OFF   11264      // [128][72] f16  = 18432 B
#define A1_OFF   29696      // [128][88] f16  = 22528 B
#define A2_OFF   29696      // [128][72] f16  = 18432 B (overlays A1)
#define OB_OFF   48128      // [128][8] f32   = 4096 B (A1 tail, dead after L1)
#define CT1_OFF  52224      // [8][64] f32    = 2048 B
#define ST1_OFF  54272      // [64] float2    = 512 B
#define ST2_OFF  54784      // [128] float2   = 1024 B
#define GROW_OFF 55808      // [128] int      = 512 B
#define SMEM_BYTES 56320

// fxh row: 72 halves = 144 B = 9 uint4 (cols 68..71 zero)
#define FXH_ROW_U4 9

// scratch (static device globals: allocation-free)
__device__ uint4  g_fxh4[(size_t)Bv * Nv * FXH_ROW_U4];
__device__ float4 g_xyzq[(size_t)Bv * Nv];
__device__ int    g_knn[(size_t)Bv * Pv * Kv];
__device__ uint4  g_wblob4[29696 / 16];            // prepacked f16 weights
__device__ float  g_ctr1[(size_t)Bv * Pv * H1v];   // center-term GEMM result

// ---- streams + events, created before harness checkpoints ----
struct HxStreams {
    cudaStream_t s2, s3;
    cudaEvent_t  eFork, eJP, eK1, eK2, eM, eT;
    HxStreams() {
        cudaStreamCreateWithFlags(&s2, cudaStreamNonBlocking);
        cudaStreamCreateWithFlags(&s3, cudaStreamNonBlocking);
        cudaEventCreateWithFlags(&eFork, cudaEventDisableTiming);
        cudaEventCreateWithFlags(&eJP, cudaEventDisableTiming);
        cudaEventCreateWithFlags(&eK1, cudaEventDisableTiming);
        cudaEventCreateWithFlags(&eK2, cudaEventDisableTiming);
        cudaEventCreateWithFlags(&eM, cudaEventDisableTiming);
        cudaEventCreateWithFlags(&eT, cudaEventDisableTiming);
    }
};
static HxStreams g_hx;

// ============================ helpers ============================
__device__ __forceinline__ uint32_t smem_to_u32(const void* p) {
    uint32_t a;
    asm("{ .reg .u64 t; cvta.to.shared.u64 t, %1; cvt.u32.u64 %0, t; }"
        : "=r"(a) : "l"(p));
    return a;
}

__device__ __forceinline__ uint32_t cvt_f16x2(float a0, float a1) {
    uint32_t d;
    asm("cvt.rn.f16x2.f32 %0, %1, %2;" : "=r"(d) : "f"(a1), "f"(a0));
    return d;
}

#define LDSM4(r0, r1, r2, r3, addr) \
    asm volatile("ldmatrix.sync.aligned.m8n8.x4.shared.b16 {%0,%1,%2,%3}, [%4];" \
        : "=r"(r0), "=r"(r1), "=r"(r2), "=r"(r3) : "r"(addr))

#define MMA_F16(d, a, b) \
    asm volatile("mma.sync.aligned.m16n8k16.row.col.f32.f16.f16.f32 " \
        "{%0,%1,%2,%3}, {%4,%5,%6,%7}, {%8,%9}, {%0,%1,%2,%3};" \
        : "+f"((d)[0]), "+f"((d)[1]), "+f"((d)[2]), "+f"((d)[3]) \
        : "r"((a)[0]), "r"((a)[1]), "r"((a)[2]), "r"((a)[3]), \
          "r"((b)[0]), "r"((b)[1]))

// warp-collective sorted-insert into a 16-lane segment. All 32 lanes execute.
__device__ __forceinline__ void seg_insert(float& v, int& vi, float dd, int ii,
                                           int lane, int seg) {
    const unsigned FULL = 0xffffffffu;
    float pv  = __shfl_up_sync(FULL, v, 1);
    int   pid = __shfl_up_sync(FULL, vi, 1);
    bool pgt = (lane > (seg ? 16 : 0)) && (pv > dd);
    bool inseg = seg ? (lane >= 16) : (lane < 16);
    if (inseg && v > dd) {
        v  = pgt ? pv  : dd;
        vi = pgt ? pid : ii;
    }
}

// full-warp ascending bitonic sort of (d, idx), one element per lane
__device__ __forceinline__ void bitonic32(float& d, int& idx, int lane) {
    const unsigned FULL = 0xffffffffu;
    #pragma unroll
    for (int k = 2; k <= 32; k <<= 1) {
        #pragma unroll
        for (int j = k >> 1; j > 0; j >>= 1) {
            float od = __shfl_xor_sync(FULL, d, j);
            int   oi = __shfl_xor_sync(FULL, idx, j);
            bool keepmin = (((lane & j) == 0) == ((lane & k) == 0));
            bool take = keepmin ? (od < d) : (od > d);
            if (take) { d = od; idx = oi; }
        }
    }
}

// evaluate NC*32 candidates at tile offset j0; min-reduce gate, eager-worst insert
template<int NC>
__device__ __forceinline__ void eval_group(
    const float4* tile, int t0, int j0, int lane,
    float ax, float ay, float az, float bx, float by, float bz,
    float& v, int& vi, float& worst0, float& worst1) {
    const unsigned FULL = 0xffffffffu;
    float d0[NC], d1[NC];
    #pragma unroll
    for (int c = 0; c < NC; c++) {
        float4 r = tile[j0 + c * 32 + lane];
        d0[c] = fmaf(r.x, ax, fmaf(r.y, ay, fmaf(r.z, az, r.w)));
        d1[c] = fmaf(r.x, bx, fmaf(r.y, by, fmaf(r.z, bz, r.w)));
    }
    float mn0 = d0[0], mn1 = d1[0];
    #pragma unroll
    for (int c = 1; c < NC; c++) { mn0 = fminf(mn0, d0[c]); mn1 = fminf(mn1, d1[c]); }
    unsigned m0 = __ballot_sync(FULL, mn0 < worst0);
    unsigned m1 = __ballot_sync(FULL, mn1 < worst1);
    while (m0) {
        int src = __ffs(m0) - 1;
        m0 &= m0 - 1;
        #pragma unroll
        for (int c = 0; c < NC; c++) {
            float dd = __shfl_sync(FULL, d0[c], src);
            if (dd < worst0) {
                seg_insert(v, vi, dd, t0 + j0 + c * 32 + src, lane, 0);
                worst0 = __shfl_sync(FULL, v, 15);
            }
        }
    }
    while (m1) {
        int src = __ffs(m1) - 1;
        m1 &= m1 - 1;
        #pragma unroll
        for (int c = 0; c < NC; c++) {
            float dd = __shfl_sync(FULL, d1[c], src);
            if (dd < worst1) {
                seg_insert(v, vi, dd, t0 + j0 + c * 32 + src, lane, 1);
                worst1 = __shfl_sync(FULL, v, 31);
            }
        }
    }
}

// ---------------------------------------------------------------------------
// Kernel A0: build packed xyzq {x,y,z,|r|^2} (knn candidate table)
// ---------------------------------------------------------------------------
__global__ void xyzq_kernel(const float* __restrict__ xyz) {
    int i = blockIdx.x * 256 + threadIdx.x;    // i < B*N
    float x = xyz[(size_t)i * 3 + 0];
    float y = xyz[(size_t)i * 3 + 1];
    float z = xyz[(size_t)i * 3 + 2];
    g_xyzq[i] = make_float4(x, y, z, fmaf(x, x, fmaf(y, y, z * z)));
}

// ---------------------------------------------------------------------------
// Kernel A: transpose feat (B,C,N) -> fxh fp16 rows (144B)
// ---------------------------------------------------------------------------
__global__ void pack_kernel(const float* __restrict__ xyz,
                            const float* __restrict__ feat) {
    __shared__ float t[64][33];
    int b  = blockIdx.y;
    int n0 = blockIdx.x * 32;
    int tx = threadIdx.x, ty = threadIdx.y;
    #pragma unroll
    for (int c0 = ty; c0 < 64; c0 += 16)
        t[c0][tx] = feat[((size_t)b * Cv + c0) * Nv + n0 + tx];
    __syncthreads();
    #pragma unroll
    for (int i = ty; i < 32; i += 16) {
        int n = n0 + i;
        uint32_t* row = (uint32_t*)(g_fxh4 + (size_t)(b * Nv + n) * FXH_ROW_U4);
        row[tx] = cvt_f16x2(t[2 * tx][i], t[2 * tx + 1][i]);
        if (tx < 4) {
            uint32_t vv = 0u;
            if (tx == 0)
                vv = cvt_f16x2(xyz[((size_t)b * Nv + n) * 3 + 0],
                               xyz[((size_t)b * Nv + n) * 3 + 1]);
            else if (tx == 1)
                vv = cvt_f16x2(xyz[((size_t)b * Nv + n) * 3 + 2], 0.f);
            row[32 + tx] = vv;
        }
    }
}

// ---------------------------------------------------------------------------
// Combo kernel: blocks [0,58): weight prepack; blocks [58,..): center GEMM
// ---------------------------------------------------------------------------
__global__ void combo_kernel(const float* __restrict__ W1,
                             const float* __restrict__ W2,
                             const float* __restrict__ xyz,
                             const float* __restrict__ feat) {
    __shared__ float cs[64 * 69 + 16 * 68];
    int bid = blockIdx.x, tid = threadIdx.x;

    if (bid < 58) {   // ---- prepack: 64*88 + 128*72 = 14848 elements ----
        int idx = bid * 256 + tid;
        unsigned short* blob = (unsigned short*)g_wblob4;
        if (idx < 64 * 88) {
            int o = idx / 88, k = idx % 88;
            float v = (k < 67) ? W1[o * 134 + k] : 0.f;
            __half h = __float2half_rn(v);
            blob[idx] = *(unsigned short*)&h;
        } else if (idx < 64 * 88 + 128 * 72) {
            int i = idx - 64 * 88;
            int o = i / 72, k = i % 72;
            float v = (k < 64) ? W2[o * 64 + k] : 0.f;
            __half h = __float2half_rn(v);
            blob[11264 / 2 + i] = *(unsigned short*)&h;
        }
        return;
    }

    // ---- center term: 16 queries x 64 outputs per block ----
    float* w1d  = cs;                 // [64][69]
    float* ctrS = cs + 64 * 69;       // [16][68]
    int q0 = (bid - 58) * 16;

    for (int idx = tid; idx < 64 * 67; idx += 256) {
        int o = idx / 67, c = idx % 67;
        w1d[o * 69 + c] = W1[o * 134 + 67 + c] - W1[o * 134 + c];
    }
    for (int idx = tid; idx < 16 * 67; idx += 256) {
        int qq = idx / 67, c = idx % 67;
        int q = q0 + qq, b = q / Pv, p = q % Pv;
        float v;
        if (c < 64) v = feat[((size_t)b * Cv + c) * Nv + p];
        else        v = xyz[((size_t)b * Nv + p) * 3 + (c - 64)];
        ctrS[qq * 68 + c] = v;
    }
    __syncthreads();

    #pragma unroll
    for (int i = 0; i < 4; i++) {
        int idx = tid + i * 256;          // 1024 outputs
        int qq = idx >> 6, n = idx & 63;
        const float* cr = ctrS + qq * 68;
        const float* wr = w1d + n * 69;
        float acc = 0.f;
        #pragma unroll
        for (int c = 0; c < 67; c++)
            acc = fmaf(cr[c], wr[c], acc);
        g_ctr1[(size_t)(q0 + qq) * 64 + n] = acc;
    }
}

// ---------------------------------------------------------------------------
// Kernel B: KNN (half grid per launch via qoff, in query pairs).
// 2 queries/warp, bitonic warm start + eager-worst inserts.
// ---------------------------------------------------------------------------
#define KTS 1024
__global__ void __launch_bounds__(256, 7) knn_kernel(int qoff) {
    __shared__ float4 tile[KTS];
    const unsigned FULL = 0xffffffffu;
    int tid  = threadIdx.x;
    int w    = tid >> 5, lane = tid & 31;
    int q0   = (qoff + blockIdx.x * 8 + w) * 2;
    int b    = q0 / Pv, p0 = q0 % Pv;
    const float4* xq = g_xyzq + (size_t)b * Nv;

    float4 qa = xq[p0], qb = xq[p0 + 1];
    float ax = -2.f * qa.x, ay = -2.f * qa.y, az = -2.f * qa.z;
    float bx = -2.f * qb.x, by = -2.f * qb.y, bz = -2.f * qb.z;

    float v;
    int   vi;
    float worst0, worst1;

    // ---- tile 0 + warm start on candidates 0..31 ----
    #pragma unroll
    for (int i = 0; i < KTS / 256; i++)
        tile[tid + i * 256] = xq[tid + i * 256];
    __syncthreads();

    {
        float4 r = tile[lane];
        float dq0 = fmaf(r.x, ax, fmaf(r.y, ay, fmaf(r.z, az, r.w)));
        float dq1 = fmaf(r.x, bx, fmaf(r.y, by, fmaf(r.z, bz, r.w)));
        int i0 = lane, i1 = lane;
        bitonic32(dq0, i0, lane);
        bitonic32(dq1, i1, lane);
        float d1s = __shfl_sync(FULL, dq1, (lane - 16) & 31);
        int   i1s = __shfl_sync(FULL, i1,  (lane - 16) & 31);
        v  = (lane < 16) ? dq0 : d1s;
        vi = (lane < 16) ? i0  : i1s;
        worst0 = __shfl_sync(FULL, v, 15);
        worst1 = __shfl_sync(FULL, v, 31);
    }

    // rest of tile 0: cands 32..127 (NC=3 group), then full 128-groups
    eval_group<3>(tile, 0, 32, lane, ax, ay, az, bx, by, bz, v, vi, worst0, worst1);
    for (int j0 = 128; j0 < KTS; j0 += 128)
        eval_group<4>(tile, 0, j0, lane, ax, ay, az, bx, by, bz, v, vi, worst0, worst1);

    // ---- remaining tiles ----
    for (int t0 = KTS; t0 < Nv; t0 += KTS) {
        __syncthreads();
        #pragma unroll
        for (int i = 0; i < KTS / 256; i++)
            tile[tid + i * 256] = xq[t0 + tid + i * 256];
        __syncthreads();
        for (int j0 = 0; j0 < KTS; j0 += 128)
            eval_group<4>(tile, t0, j0, lane, ax, ay, az, bx, by, bz, v, vi, worst0, worst1);
    }

    if (lane < 16) g_knn[(size_t)q0 * Kv + lane] = vi;
    else           g_knn[(size_t)(q0 + 1) * Kv + lane - 16] = vi;
}

// ---------------------------------------------------------------------------
// Kernel C: tensor-core MLP (half grid per launch via blkoff).
// Single fp16 weights, load-and-consume W frags, OB overlaid into A1 tail.
// ---------------------------------------------------------------------------
__global__ void __launch_bounds__(256, 4) mlp_kernel(
    const float* __restrict__ b1, const float* __restrict__ g1,
    const float* __restrict__ be1, const float* __restrict__ m1,
    const float* __restrict__ v1,
    const float* __restrict__ b2, const float* __restrict__ g2,
    const float* __restrict__ be2, const float* __restrict__ m2,
    const float* __restrict__ v2,
    float* __restrict__ out, int blkoff) {
    extern __shared__ unsigned char smem[];
    uint32_t sb = smem_to_u32(smem);
    int tid = threadIdx.x;
    int w = tid >> 5, l = tid & 31;
    int blk = blockIdx.x + blkoff;

    // weights blob -> smem
    for (int i = tid; i < 29696 / 16; i += 256)
        ((uint4*)smem)[i] = g_wblob4[i];

    float2* ST1 = (float2*)(smem + ST1_OFF);
    float2* ST2 = (float2*)(smem + ST2_OFF);
    if (tid < 64) {
        float s = g1[tid] * rsqrtf(v1[tid] + EPSv);
        ST1[tid] = make_float2(s, fmaf(s, b1[tid] - m1[tid], be1[tid]));
    }
    if (tid < 128) {
        float s = g2[tid] * rsqrtf(v2[tid] + EPSv);
        ST2[tid] = make_float2(s, fmaf(s, b2[tid] - m2[tid], be2[tid]));
    }

    int pbase = (blk * 8) & (Pv - 1);
    int bblk  = (blk * 8) >> 11;

    // center terms for the 8 points
    float* CT = (float*)(smem + CT1_OFF);
    #pragma unroll
    for (int i = 0; i < 2; i++) {
        int idx = tid + i * 256;
        CT[idx] = g_ctr1[(size_t)(bblk * Pv + pbase + (idx >> 6)) * 64 + (idx & 63)];
    }

    // neighbor global-row table (128 rows)
    int* grow = (int*)(smem + GROW_OFF);
    if (tid < 128) {
        int pt = tid >> 4, k = tid & 15;
        grow[tid] = bblk * Nv + g_knn[((size_t)bblk * Pv + pbase + pt) * Kv + k];
    }
    __syncthreads();

    // ---- gather: pure fp16 uint4 copy (128 rows x 9 uint4) ----
    #pragma unroll
    for (int i = 0; i < 5; i++) {
        int idx = tid + i * 256;          // 1152 total
        if (idx < 1152) {
            int row = idx / 9, q = idx % 9;
            uint4 val = g_fxh4[(size_t)grow[row] * FXH_ROW_U4 + q];
            *(uint4*)(smem + A1_OFF + row * 176 + q * 16) = val;
        }
    }
    if (tid < 128) {   // zero cols 72..79 (bytes 144..159)
        uint4 z = make_uint4(0, 0, 0, 0);
        *(uint4*)(smem + A1_OFF + tid * 176 + 144) = z;
    }
    __syncthreads();

    int mrow = 16 * w;   // warp w owns rows [16w, 16w+16) = point w's neighbors
    uint32_t a1_l = (mrow + (l & 15)) * 176 + (l >> 4) * 16;
    uint32_t b1_l = ((l & 7) + ((l >> 4) << 3)) * 176 + ((l >> 3) & 1) * 16;

    // ---- layer1: K=80, W frags loaded-and-consumed ----
    float acc1[8][4];
    #pragma unroll
    for (int j = 0; j < 8; j++)
        #pragma unroll
        for (int r = 0; r < 4; r++) acc1[j][r] = 0.f;

    #pragma unroll
    for (int ks = 0; ks < 5; ks++) {
        uint32_t a0[4];
        LDSM4(a0[0], a0[1], a0[2], a0[3], sb + A1_OFF + a1_l + ks * 32);
        #pragma unroll
        for (int jj = 0; jj < 4; jj++) {
            uint32_t r0, r1, r2, r3;
            LDSM4(r0, r1, r2, r3, sb + W1_OFF + b1_l + jj * (16 * 176) + ks * 32);
            uint32_t bA[2] = {r0, r1};
            uint32_t bB[2] = {r2, r3};
            MMA_F16(acc1[2 * jj],     a0, bA);
            MMA_F16(acc1[2 * jj + 1], a0, bB);
        }
    }

    // all warps' layer1 ldmatrix done -> safe to overwrite A1 with A2
    __syncthreads();

    // ---- epilogue1: +center, BN, ReLU, fp16, store A2 directly ----
    int ce = 2 * (l & 3);
    const float* ctp = CT + w * 64;
    {
        uint32_t rowb = (mrow + (l >> 2)) * 144;
        #pragma unroll
        for (int j = 0; j < 8; j++) {
            int n = 8 * j + ce;
            float2 se = ST1[n], so = ST1[n + 1];
            float2 ct = *(const float2*)(ctp + n);
            float v0 = fmaxf(fmaf(se.x, acc1[j][0] + ct.x, se.y), 0.f);
            float v1 = fmaxf(fmaf(so.x, acc1[j][1] + ct.y, so.y), 0.f);
            float v2 = fmaxf(fmaf(se.x, acc1[j][2] + ct.x, se.y), 0.f);
            float v3 = fmaxf(fmaf(so.x, acc1[j][3] + ct.y, so.y), 0.f);
            uint32_t off = rowb + (8 * j + ce) * 2;
            *(uint32_t*)(smem + A2_OFF + off)           = cvt_f16x2(v0, v1);
            *(uint32_t*)(smem + A2_OFF + off + 8 * 144) = cvt_f16x2(v2, v3);
        }
    }
    __syncthreads();

    // ---- layer2: K=64, N=128 in two halves; epilogue max over k ----
    float* OBf = (float*)(smem + OB_OFF);
    uint32_t a2_l = (mrow + (l & 15)) * 144 + (l >> 4) * 16;
    uint32_t b2_l = ((l & 7) + ((l >> 4) << 3)) * 144 + ((l >> 3) & 1) * 16;

    #pragma unroll
    for (int h = 0; h < 2; h++) {
        float acc2[8][4];
        #pragma unroll
        for (int j = 0; j < 8; j++)
            #pragma unroll
            for (int r = 0; r < 4; r++) acc2[j][r] = 0.f;

        #pragma unroll
        for (int ks = 0; ks < 4; ks++) {
            uint32_t a0[4];
            LDSM4(a0[0], a0[1], a0[2], a0[3], sb + A2_OFF + a2_l + ks * 32);
            uint32_t Wb = sb + W2_OFF + h * (64 * 144);
            #pragma unroll
            for (int jj = 0; jj < 4; jj++) {
                uint32_t r0, r1, r2, r3;
                LDSM4(r0, r1, r2, r3, Wb + b2_l + jj * (16 * 144) + ks * 32);
                uint32_t bA[2] = {r0, r1};
                uint32_t bB[2] = {r2, r3};
                MMA_F16(acc2[2 * jj],     a0, bA);
                MMA_F16(acc2[2 * jj + 1], a0, bB);
            }
        }

        // epilogue2: BN+ReLU, max over 16 k-rows (all within this warp)
        #pragma unroll
        for (int j = 0; j < 8; j++) {
            int n = 64 * h + 8 * j + ce;
            float2 se = ST2[n], so = ST2[n + 1];
            float v0 = fmaxf(fmaf(se.x, acc2[j][0], se.y), 0.f);
            float v1 = fmaxf(fmaf(so.x, acc2[j][1], so.y), 0.f);
            float v2 = fmaxf(fmaf(se.x, acc2[j][2], se.y), 0.f);
            float v3 = fmaxf(fmaf(so.x, acc2[j][3], so.y), 0.f);
            float m0 = fmaxf(v0, v2);
            float m1 = fmaxf(v1, v3);
            #pragma unroll
            for (int d = 4; d < 32; d <<= 1) {
                m0 = fmaxf(m0, __shfl_xor_sync(0xffffffffu, m0, d));
                m1 = fmaxf(m1, __shfl_xor_sync(0xffffffffu, m1, d));
            }
            if (l < 4) {
                OBf[n * 8 + w]       = m0;
                OBf[(n + 1) * 8 + w] = m1;
            }
        }
    }
    __syncthreads();

    // ---- coalesced output: new_feat (B, 128, P), after new_xyz ----
    float* outF = out + (size_t)Bv * Pv * 3;
    for (int r = tid; r < 128 * 8; r += 256) {
        int j = r >> 3, pi = r & 7;
        outF[((size_t)bblk * H2v + j) * Pv + pbase + pi] = OBf[r];
    }
}

// ---------------------------------------------------------------------------
// Kernel D: new_xyz copy + sample_idx (merged)
// ---------------------------------------------------------------------------
__global__ void tail_kernel(const float* __restrict__ xyz, float* __restrict__ out) {
    int i = blockIdx.x * 256 + threadIdx.x;
    const int NX = Bv * Pv * 3;
    if (i < NX) {
        int d = i % 3; int rem = i / 3; int p = rem % Pv; int b = rem / Pv;
        out[i] = xyz[((size_t)b * Nv + p) * 3 + d];
    } else if (i < NX + Bv * Pv) {
        int j = i - NX;
        out[(size_t)NX + (size_t)Bv * H2v * Pv + j] = (float)(j % Pv);
    }
}

// ---------------------------------------------------------------------------
extern "C" void kernel_launch(void* const* d_in, const int* in_sizes, int n_in,
                              void* d_out, int out_size) {
    const float* xyz  = (const float*)d_in[0];
    const float* feat = (const float*)d_in[1];
    const float* W1   = (const float*)d_in[2];
    const float* b1   = (const float*)d_in[3];
    const float* g1   = (const float*)d_in[4];
    const float* be1  = (const float*)d_in[5];
    const float* m1   = (const float*)d_in[6];
    const float* v1   = (const float*)d_in[7];
    const float* W2   = (const float*)d_in[8];
    const float* b2   = (const float*)d_in[9];
    const float* g2   = (const float*)d_in[10];
    const float* be2  = (const float*)d_in[11];
    const float* m2   = (const float*)d_in[12];
    const float* v2   = (const float*)d_in[13];
    float* out = (float*)d_out;

    cudaFuncSetAttribute(mlp_kernel, cudaFuncAttributeMaxDynamicSharedMemorySize,
                         SMEM_BYTES);

    cudaStream_t s0 = (cudaStream_t)0;
    const int KNN_HALF = (Bv * Pv) / 32;   // 512 blocks (8192 query pairs / 16 per blk)
    const int MLP_HALF = (Bv * Pv) / 16;   // 1024 blocks

    // fork side streams from s0
    cudaEventRecord(g_hx.eFork, s0);
    cudaStreamWaitEvent(g_hx.s2, g_hx.eFork, 0);
    cudaStreamWaitEvent(g_hx.s3, g_hx.eFork, 0);

    xyzq_kernel<<<(Bv * Nv) / 256, 256, 0, s0>>>(xyz);                          // #1
    pack_kernel<<<dim3(Nv / 32, Bv), dim3(32, 16), 0, g_hx.s2>>>(xyz, feat);    // #2
    combo_kernel<<<58 + (Bv * Pv) / 16, 256, 0, g_hx.s2>>>(W1, W2, xyz, feat);  // #3
    cudaEventRecord(g_hx.eJP, g_hx.s2);

    knn_kernel<<<KNN_HALF, 256, 0, s0>>>(0);                                    // #4 (ncu slot)
    cudaEventRecord(g_hx.eK1, s0);
    knn_kernel<<<KNN_HALF, 256, 0, s0>>>(Bv * Pv / 4);                          // #5
    cudaEventRecord(g_hx.eK2, s0);

    // mlp pipeline on s3: first half overlaps knn second half
    cudaStreamWaitEvent(g_hx.s3, g_hx.eK1, 0);
    cudaStreamWaitEvent(g_hx.s3, g_hx.eJP, 0);
    mlp_kernel<<<MLP_HALF, 256, SMEM_BYTES, g_hx.s3>>>(b1, g1, be1, m1, v1,
                                                       b2, g2, be2, m2, v2, out, 0);        // #6
    cudaStreamWaitEvent(g_hx.s3, g_hx.eK2, 0);
    mlp_kernel<<<MLP_HALF, 256, SMEM_BYTES, g_hx.s3>>>(b1, g1, be1, m1, v1,
                                                       b2, g2, be2, m2, v2, out, MLP_HALF); // #7
    cudaEventRecord(g_hx.eM, g_hx.s3);

    tail_kernel<<<256, 256, 0, g_hx.s2>>>(xyz, out);                            // #8
    cudaEventRecord(g_hx.eT, g_hx.s2);

    // join everything back to s0
    cudaStreamWaitEvent(s0, g_hx.eM, 0);
    cudaStreamWaitEvent(s0, g_hx.eT, 0);
}

// round 16
// speedup vs baseline: 1.2086x; 1.2086x over previous
#include <cuda_runtime.h>
#include <cuda_fp16.h>
#include <math.h>
#include <stdint.h>

#define Bv   8
#define Nv   8192
#define Cv   64
#define Pv   2048
#define Kv   16
#define H1v  64
#define H2v  128
#define EPSv 1e-5f

// ---- smem byte offsets for mlp kernel (OB overlaid into A1 tail) ----
#define W1_OFF   0          // [64][88] f16   = 11264 B
#define W2_OFF   11264      // [128][72] f16  = 18432 B
#define A1_OFF   29696      // [128][88] f16  = 22528 B
#define A2_OFF   29696      // [128][72] f16  = 18432 B (overlays A1)
#define OB_OFF   48128      // [128][8] f32   = 4096 B (A1 tail, dead after L1)
#define CT1_OFF  52224      // [8][64] f32    = 2048 B
#define ST1_OFF  54272      // [64] float2    = 512 B
#define ST2_OFF  54784      // [128] float2   = 1024 B
#define GROW_OFF 55808      // [128] int      = 512 B
#define SMEM_BYTES 56320

// fxh row: 72 halves = 144 B = 9 uint4 (cols 68..71 zero)
#define FXH_ROW_U4 9

// scratch (static device globals: allocation-free)
__device__ uint4  g_fxh4[(size_t)Bv * Nv * FXH_ROW_U4];
__device__ float4 g_xyzq[(size_t)Bv * Nv];
__device__ int    g_knn[(size_t)Bv * Pv * Kv];
__device__ uint4  g_wblob4[29696 / 16];            // prepacked f16 weights
__device__ float  g_ctr1[(size_t)Bv * Pv * H1v];   // center-term GEMM result

// ---- side stream + events, created before harness checkpoints ----
struct HxStreams {
    cudaStream_t s2;
    cudaEvent_t  eFork, eJoin, eJoin2;
    HxStreams() {
        cudaStreamCreateWithFlags(&s2, cudaStreamNonBlocking);
        cudaEventCreateWithFlags(&eFork, cudaEventDisableTiming);
        cudaEventCreateWithFlags(&eJoin, cudaEventDisableTiming);
        cudaEventCreateWithFlags(&eJoin2, cudaEventDisableTiming);
    }
};
static HxStreams g_hx;

// ============================ helpers ============================
__device__ __forceinline__ uint32_t smem_to_u32(const void* p) {
    uint32_t a;
    asm("{ .reg .u64 t; cvta.to.shared.u64 t, %1; cvt.u32.u64 %0, t; }"
        : "=r"(a) : "l"(p));
    return a;
}

__device__ __forceinline__ uint32_t cvt_f16x2(float a0, float a1) {
    uint32_t d;
    asm("cvt.rn.f16x2.f32 %0, %1, %2;" : "=r"(d) : "f"(a1), "f"(a0));
    return d;
}

#define LDSM4(r0, r1, r2, r3, addr) \
    asm volatile("ldmatrix.sync.aligned.m8n8.x4.shared.b16 {%0,%1,%2,%3}, [%4];" \
        : "=r"(r0), "=r"(r1), "=r"(r2), "=r"(r3) : "r"(addr))

#define MMA_F16(d, a, b) \
    asm volatile("mma.sync.aligned.m16n8k16.row.col.f32.f16.f16.f32 " \
        "{%0,%1,%2,%3}, {%4,%5,%6,%7}, {%8,%9}, {%0,%1,%2,%3};" \
        : "+f"((d)[0]), "+f"((d)[1]), "+f"((d)[2]), "+f"((d)[3]) \
        : "r"((a)[0]), "r"((a)[1]), "r"((a)[2]), "r"((a)[3]), \
          "r"((b)[0]), "r"((b)[1]))

// warp-collective sorted-insert into a 16-lane segment. All 32 lanes execute.
__device__ __forceinline__ void seg_insert(float& v, int& vi, float dd, int ii,
                                           int lane, int seg) {
    const unsigned FULL = 0xffffffffu;
    float pv  = __shfl_up_sync(FULL, v, 1);
    int   pid = __shfl_up_sync(FULL, vi, 1);
    bool pgt = (lane > (seg ? 16 : 0)) && (pv > dd);
    bool inseg = seg ? (lane >= 16) : (lane < 16);
    if (inseg && v > dd) {
        v  = pgt ? pv  : dd;
        vi = pgt ? pid : ii;
    }
}

// full-warp ascending bitonic sort of (d, idx), one element per lane
__device__ __forceinline__ void bitonic32(float& d, int& idx, int lane) {
    const unsigned FULL = 0xffffffffu;
    #pragma unroll
    for (int k = 2; k <= 32; k <<= 1) {
        #pragma unroll
        for (int j = k >> 1; j > 0; j >>= 1) {
            float od = __shfl_xor_sync(FULL, d, j);
            int   oi = __shfl_xor_sync(FULL, idx, j);
            bool keepmin = (((lane & j) == 0) == ((lane & k) == 0));
            bool take = keepmin ? (od < d) : (od > d);
            if (take) { d = od; idx = oi; }
        }
    }
}

// evaluate NC*32 candidates at tile offset j0; min-reduce gate, eager-worst insert
template<int NC>
__device__ __forceinline__ void eval_group(
    const float4* tile, int t0, int j0, int lane,
    float ax, float ay, float az, float bx, float by, float bz,
    float& v, int& vi, float& worst0, float& worst1) {
    const unsigned FULL = 0xffffffffu;
    float d0[NC], d1[NC];
    #pragma unroll
    for (int c = 0; c < NC; c++) {
        float4 r = tile[j0 + c * 32 + lane];
        d0[c] = fmaf(r.x, ax, fmaf(r.y, ay, fmaf(r.z, az, r.w)));
        d1[c] = fmaf(r.x, bx, fmaf(r.y, by, fmaf(r.z, bz, r.w)));
    }
    float mn0 = d0[0], mn1 = d1[0];
    #pragma unroll
    for (int c = 1; c < NC; c++) { mn0 = fminf(mn0, d0[c]); mn1 = fminf(mn1, d1[c]); }
    unsigned m0 = __ballot_sync(FULL, mn0 < worst0);
    unsigned m1 = __ballot_sync(FULL, mn1 < worst1);
    while (m0) {
        int src = __ffs(m0) - 1;
        m0 &= m0 - 1;
        #pragma unroll
        for (int c = 0; c < NC; c++) {
            float dd = __shfl_sync(FULL, d0[c], src);
            if (dd < worst0) {
                seg_insert(v, vi, dd, t0 + j0 + c * 32 + src, lane, 0);
                worst0 = __shfl_sync(FULL, v, 15);
            }
        }
    }
    while (m1) {
        int src = __ffs(m1) - 1;
        m1 &= m1 - 1;
        #pragma unroll
        for (int c = 0; c < NC; c++) {
            float dd = __shfl_sync(FULL, d1[c], src);
            if (dd < worst1) {
                seg_insert(v, vi, dd, t0 + j0 + c * 32 + src, lane, 1);
                worst1 = __shfl_sync(FULL, v, 31);
            }
        }
    }
}

// ---------------------------------------------------------------------------
// Kernel A0: build packed xyzq {x,y,z,|r|^2} (knn candidate table)
// ---------------------------------------------------------------------------
__global__ void xyzq_kernel(const float* __restrict__ xyz) {
    int i = blockIdx.x * 256 + threadIdx.x;    // i < B*N
    float x = xyz[(size_t)i * 3 + 0];
    float y = xyz[(size_t)i * 3 + 1];
    float z = xyz[(size_t)i * 3 + 2];
    g_xyzq[i] = make_float4(x, y, z, fmaf(x, x, fmaf(y, y, z * z)));
}

// ---------------------------------------------------------------------------
// Kernel A: transpose feat (B,C,N) -> fxh fp16 rows (144B)
// ---------------------------------------------------------------------------
__global__ void pack_kernel(const float* __restrict__ xyz,
                            const float* __restrict__ feat) {
    __shared__ float t[64][33];
    int b  = blockIdx.y;
    int n0 = blockIdx.x * 32;
    int tx = threadIdx.x, ty = threadIdx.y;
    #pragma unroll
    for (int c0 = ty; c0 < 64; c0 += 16)
        t[c0][tx] = feat[((size_t)b * Cv + c0) * Nv + n0 + tx];
    __syncthreads();
    #pragma unroll
    for (int i = ty; i < 32; i += 16) {
        int n = n0 + i;
        uint32_t* row = (uint32_t*)(g_fxh4 + (size_t)(b * Nv + n) * FXH_ROW_U4);
        row[tx] = cvt_f16x2(t[2 * tx][i], t[2 * tx + 1][i]);
        if (tx < 4) {
            uint32_t vv = 0u;
            if (tx == 0)
                vv = cvt_f16x2(xyz[((size_t)b * Nv + n) * 3 + 0],
                               xyz[((size_t)b * Nv + n) * 3 + 1]);
            else if (tx == 1)
                vv = cvt_f16x2(xyz[((size_t)b * Nv + n) * 3 + 2], 0.f);
            row[32 + tx] = vv;
        }
    }
}

// ---------------------------------------------------------------------------
// Combo kernel: blocks [0,58): weight prepack; blocks [58,..): center GEMM
// ---------------------------------------------------------------------------
__global__ void combo_kernel(const float* __restrict__ W1,
                             const float* __restrict__ W2,
                             const float* __restrict__ xyz,
                             const float* __restrict__ feat) {
    __shared__ float cs[64 * 69 + 16 * 68];
    int bid = blockIdx.x, tid = threadIdx.x;

    if (bid < 58) {   // ---- prepack: 64*88 + 128*72 = 14848 elements ----
        int idx = bid * 256 + tid;
        unsigned short* blob = (unsigned short*)g_wblob4;
        if (idx < 64 * 88) {
            int o = idx / 88, k = idx % 88;
            float v = (k < 67) ? W1[o * 134 + k] : 0.f;
            __half h = __float2half_rn(v);
            blob[idx] = *(unsigned short*)&h;
        } else if (idx < 64 * 88 + 128 * 72) {
            int i = idx - 64 * 88;
            int o = i / 72, k = i % 72;
            float v = (k < 64) ? W2[o * 64 + k] : 0.f;
            __half h = __float2half_rn(v);
            blob[11264 / 2 + i] = *(unsigned short*)&h;
        }
        return;
    }

    // ---- center term: 16 queries x 64 outputs per block ----
    float* w1d  = cs;                 // [64][69]
    float* ctrS = cs + 64 * 69;       // [16][68]
    int q0 = (bid - 58) * 16;

    for (int idx = tid; idx < 64 * 67; idx += 256) {
        int o = idx / 67, c = idx % 67;
        w1d[o * 69 + c] = W1[o * 134 + 67 + c] - W1[o * 134 + c];
    }
    for (int idx = tid; idx < 16 * 67; idx += 256) {
        int qq = idx / 67, c = idx % 67;
        int q = q0 + qq, b = q / Pv, p = q % Pv;
        float v;
        if (c < 64) v = feat[((size_t)b * Cv + c) * Nv + p];
        else        v = xyz[((size_t)b * Nv + p) * 3 + (c - 64)];
        ctrS[qq * 68 + c] = v;
    }
    __syncthreads();

    #pragma unroll
    for (int i = 0; i < 4; i++) {
        int idx = tid + i * 256;          // 1024 outputs
        int qq = idx >> 6, n = idx & 63;
        const float* cr = ctrS + qq * 68;
        const float* wr = w1d + n * 69;
        float acc = 0.f;
        #pragma unroll
        for (int c = 0; c < 67; c++)
            acc = fmaf(cr[c], wr[c], acc);
        g_ctr1[(size_t)(q0 + qq) * 64 + n] = acc;
    }
}

// ---------------------------------------------------------------------------
// Kernel B: KNN, full grid (1024 blocks, one wave), 2 queries/warp,
// bitonic warm start + eager-worst inserts. (round-12 measured config)
// ---------------------------------------------------------------------------
#define KTS 1024
__global__ void __launch_bounds__(256, 7) knn_kernel() {
    __shared__ float4 tile[KTS];
    const unsigned FULL = 0xffffffffu;
    int tid  = threadIdx.x;
    int w    = tid >> 5, lane = tid & 31;
    int q0   = (blockIdx.x * 8 + w) * 2;
    int b    = q0 / Pv, p0 = q0 % Pv;
    const float4* xq = g_xyzq + (size_t)b * Nv;

    float4 qa = xq[p0], qb = xq[p0 + 1];
    float ax = -2.f * qa.x, ay = -2.f * qa.y, az = -2.f * qa.z;
    float bx = -2.f * qb.x, by = -2.f * qb.y, bz = -2.f * qb.z;

    float v;
    int   vi;
    float worst0, worst1;

    // ---- tile 0 + warm start on candidates 0..31 ----
    #pragma unroll
    for (int i = 0; i < KTS / 256; i++)
        tile[tid + i * 256] = xq[tid + i * 256];
    __syncthreads();

    {
        float4 r = tile[lane];
        float dq0 = fmaf(r.x, ax, fmaf(r.y, ay, fmaf(r.z, az, r.w)));
        float dq1 = fmaf(r.x, bx, fmaf(r.y, by, fmaf(r.z, bz, r.w)));
        int i0 = lane, i1 = lane;
        bitonic32(dq0, i0, lane);
        bitonic32(dq1, i1, lane);
        float d1s = __shfl_sync(FULL, dq1, (lane - 16) & 31);
        int   i1s = __shfl_sync(FULL, i1,  (lane - 16) & 31);
        v  = (lane < 16) ? dq0 : d1s;
        vi = (lane < 16) ? i0  : i1s;
        worst0 = __shfl_sync(FULL, v, 15);
        worst1 = __shfl_sync(FULL, v, 31);
    }

    // rest of tile 0: cands 32..127 (NC=3 group), then full 128-groups
    eval_group<3>(tile, 0, 32, lane, ax, ay, az, bx, by, bz, v, vi, worst0, worst1);
    for (int j0 = 128; j0 < KTS; j0 += 128)
        eval_group<4>(tile, 0, j0, lane, ax, ay, az, bx, by, bz, v, vi, worst0, worst1);

    // ---- remaining tiles ----
    for (int t0 = KTS; t0 < Nv; t0 += KTS) {
        __syncthreads();
        #pragma unroll
        for (int i = 0; i < KTS / 256; i++)
            tile[tid + i * 256] = xq[t0 + tid + i * 256];
        __syncthreads();
        for (int j0 = 0; j0 < KTS; j0 += 128)
            eval_group<4>(tile, t0, j0, lane, ax, ay, az, bx, by, bz, v, vi, worst0, worst1);
    }

    if (lane < 16) g_knn[(size_t)q0 * Kv + lane] = vi;
    else           g_knn[(size_t)(q0 + 1) * Kv + lane - 16] = vi;
}

// ---------------------------------------------------------------------------
// Kernel C: tensor-core MLP, 4 CTAs/SM, 2 point-groups per CTA (weights and
// BN folds loaded once, amortized over 16 points).
// ---------------------------------------------------------------------------
__global__ void __launch_bounds__(256, 4) mlp_kernel(
    const float* __restrict__ b1, const float* __restrict__ g1,
    const float* __restrict__ be1, const float* __restrict__ m1,
    const float* __restrict__ v1,
    const float* __restrict__ b2, const float* __restrict__ g2,
    const float* __restrict__ be2, const float* __restrict__ m2,
    const float* __restrict__ v2,
    float* __restrict__ out) {
    extern __shared__ unsigned char smem[];
    uint32_t sb = smem_to_u32(smem);
    int tid = threadIdx.x;
    int w = tid >> 5, l = tid & 31;

    // weights blob -> smem (once per CTA, serves both point-groups)
    for (int i = tid; i < 29696 / 16; i += 256)
        ((uint4*)smem)[i] = g_wblob4[i];

    float2* ST1 = (float2*)(smem + ST1_OFF);
    float2* ST2 = (float2*)(smem + ST2_OFF);
    if (tid < 64) {
        float s = g1[tid] * rsqrtf(v1[tid] + EPSv);
        ST1[tid] = make_float2(s, fmaf(s, b1[tid] - m1[tid], be1[tid]));
    }
    if (tid < 128) {
        float s = g2[tid] * rsqrtf(v2[tid] + EPSv);
        ST2[tid] = make_float2(s, fmaf(s, b2[tid] - m2[tid], be2[tid]));
    }

    int mrow = 16 * w;   // warp w owns rows [16w, 16w+16) = point w's neighbors
    uint32_t a1_l = (mrow + (l & 15)) * 176 + (l >> 4) * 16;
    uint32_t b1_l = ((l & 7) + ((l >> 4) << 3)) * 176 + ((l >> 3) & 1) * 16;
    uint32_t a2_l = (mrow + (l & 15)) * 144 + (l >> 4) * 16;
    uint32_t b2_l = ((l & 7) + ((l >> 4) << 3)) * 144 + ((l >> 3) & 1) * 16;
    int ce = 2 * (l & 3);
    float* CT  = (float*)(smem + CT1_OFF);
    int*   grow = (int*)(smem + GROW_OFF);
    float* OBf = (float*)(smem + OB_OFF);

    #pragma unroll 1
    for (int it = 0; it < 2; it++) {
        int blk   = blockIdx.x * 2 + it;
        int pbase = (blk * 8) & (Pv - 1);
        int bblk  = (blk * 8) >> 11;

        // center terms + neighbor row table for this group
        #pragma unroll
        for (int i = 0; i < 2; i++) {
            int idx = tid + i * 256;
            CT[idx] = g_ctr1[(size_t)(bblk * Pv + pbase + (idx >> 6)) * 64 + (idx & 63)];
        }
        if (tid < 128) {
            int pt = tid >> 4, k = tid & 15;
            grow[tid] = bblk * Nv + g_knn[((size_t)bblk * Pv + pbase + pt) * Kv + k];
        }
        __syncthreads();

        // ---- gather: pure fp16 uint4 copy (128 rows x 9 uint4) ----
        #pragma unroll
        for (int i = 0; i < 5; i++) {
            int idx = tid + i * 256;          // 1152 total
            if (idx < 1152) {
                int row = idx / 9, q = idx % 9;
                uint4 val = g_fxh4[(size_t)grow[row] * FXH_ROW_U4 + q];
                *(uint4*)(smem + A1_OFF + row * 176 + q * 16) = val;
            }
        }
        if (tid < 128) {   // zero cols 72..79 (bytes 144..159)
            uint4 z = make_uint4(0, 0, 0, 0);
            *(uint4*)(smem + A1_OFF + tid * 176 + 144) = z;
        }
        __syncthreads();

        // ---- layer1: K=80, W frags loaded-and-consumed ----
        float acc1[8][4];
        #pragma unroll
        for (int j = 0; j < 8; j++)
            #pragma unroll
            for (int r = 0; r < 4; r++) acc1[j][r] = 0.f;

        #pragma unroll
        for (int ks = 0; ks < 5; ks++) {
            uint32_t a0[4];
            LDSM4(a0[0], a0[1], a0[2], a0[3], sb + A1_OFF + a1_l + ks * 32);
            #pragma unroll
            for (int jj = 0; jj < 4; jj++) {
                uint32_t r0, r1, r2, r3;
                LDSM4(r0, r1, r2, r3, sb + W1_OFF + b1_l + jj * (16 * 176) + ks * 32);
                uint32_t bA[2] = {r0, r1};
                uint32_t bB[2] = {r2, r3};
                MMA_F16(acc1[2 * jj],     a0, bA);
                MMA_F16(acc1[2 * jj + 1], a0, bB);
            }
        }

        // all warps' layer1 ldmatrix done -> safe to overwrite A1 with A2
        __syncthreads();

        // ---- epilogue1: +center, BN, ReLU, fp16, store A2 directly ----
        const float* ctp = CT + w * 64;
        {
            uint32_t rowb = (mrow + (l >> 2)) * 144;
            #pragma unroll
            for (int j = 0; j < 8; j++) {
                int n = 8 * j + ce;
                float2 se = ST1[n], so = ST1[n + 1];
                float2 ct = *(const float2*)(ctp + n);
                float v0 = fmaxf(fmaf(se.x, acc1[j][0] + ct.x, se.y), 0.f);
                float v1 = fmaxf(fmaf(so.x, acc1[j][1] + ct.y, so.y), 0.f);
                float v2 = fmaxf(fmaf(se.x, acc1[j][2] + ct.x, se.y), 0.f);
                float v3 = fmaxf(fmaf(so.x, acc1[j][3] + ct.y, so.y), 0.f);
                uint32_t off = rowb + (8 * j + ce) * 2;
                *(uint32_t*)(smem + A2_OFF + off)           = cvt_f16x2(v0, v1);
                *(uint32_t*)(smem + A2_OFF + off + 8 * 144) = cvt_f16x2(v2, v3);
            }
        }
        __syncthreads();

        // ---- layer2: K=64, N=128 in two halves; epilogue max over k ----
        #pragma unroll
        for (int h = 0; h < 2; h++) {
            float acc2[8][4];
            #pragma unroll
            for (int j = 0; j < 8; j++)
                #pragma unroll
                for (int r = 0; r < 4; r++) acc2[j][r] = 0.f;

            #pragma unroll
            for (int ks = 0; ks < 4; ks++) {
                uint32_t a0[4];
                LDSM4(a0[0], a0[1], a0[2], a0[3], sb + A2_OFF + a2_l + ks * 32);
                uint32_t Wb = sb + W2_OFF + h * (64 * 144);
                #pragma unroll
                for (int jj = 0; jj < 4; jj++) {
                    uint32_t r0, r1, r2, r3;
                    LDSM4(r0, r1, r2, r3, Wb + b2_l + jj * (16 * 144) + ks * 32);
                    uint32_t bA[2] = {r0, r1};
                    uint32_t bB[2] = {r2, r3};
                    MMA_F16(acc2[2 * jj],     a0, bA);
                    MMA_F16(acc2[2 * jj + 1], a0, bB);
                }
            }

            // epilogue2: BN+ReLU, max over 16 k-rows (all within this warp)
            #pragma unroll
            for (int j = 0; j < 8; j++) {
                int n = 64 * h + 8 * j + ce;
                float2 se = ST2[n], so = ST2[n + 1];
                float v0 = fmaxf(fmaf(se.x, acc2[j][0], se.y), 0.f);
                float v1 = fmaxf(fmaf(so.x, acc2[j][1], so.y), 0.f);
                float v2 = fmaxf(fmaf(se.x, acc2[j][2], se.y), 0.f);
                float v3 = fmaxf(fmaf(so.x, acc2[j][3], so.y), 0.f);
                float m0 = fmaxf(v0, v2);
                float m1 = fmaxf(v1, v3);
                #pragma unroll
                for (int d = 4; d < 32; d <<= 1) {
                    m0 = fmaxf(m0, __shfl_xor_sync(0xffffffffu, m0, d));
                    m1 = fmaxf(m1, __shfl_xor_sync(0xffffffffu, m1, d));
                }
                if (l < 4) {
                    OBf[n * 8 + w]       = m0;
                    OBf[(n + 1) * 8 + w] = m1;
                }
            }
        }
        __syncthreads();

        // ---- coalesced output: new_feat (B, 128, P), after new_xyz ----
        float* outF = out + (size_t)Bv * Pv * 3;
        for (int r = tid; r < 128 * 8; r += 256) {
            int j = r >> 3, pi = r & 7;
            outF[((size_t)bblk * H2v + j) * Pv + pbase + pi] = OBf[r];
        }
        __syncthreads();   // OBf/A1 fully consumed before next group's gather
    }
}

// ---------------------------------------------------------------------------
// Kernel D: new_xyz copy + sample_idx (merged)
// ---------------------------------------------------------------------------
__global__ void tail_kernel(const float* __restrict__ xyz, float* __restrict__ out) {
    int i = blockIdx.x * 256 + threadIdx.x;
    const int NX = Bv * Pv * 3;
    if (i < NX) {
        int d = i % 3; int rem = i / 3; int p = rem % Pv; int b = rem / Pv;
        out[i] = xyz[((size_t)b * Nv + p) * 3 + d];
    } else if (i < NX + Bv * Pv) {
        int j = i - NX;
        out[(size_t)NX + (size_t)Bv * H2v * Pv + j] = (float)(j % Pv);
    }
}

// ---------------------------------------------------------------------------
extern "C" void kernel_launch(void* const* d_in, const int* in_sizes, int n_in,
                              void* d_out, int out_size) {
    const float* xyz  = (const float*)d_in[0];
    const float* feat = (const float*)d_in[1];
    const float* W1   = (const float*)d_in[2];
    const float* b1   = (const float*)d_in[3];
    const float* g1   = (const float*)d_in[4];
    const float* be1  = (const float*)d_in[5];
    const float* m1   = (const float*)d_in[6];
    const float* v1   = (const float*)d_in[7];
    const float* W2   = (const float*)d_in[8];
    const float* b2   = (const float*)d_in[9];
    const float* g2   = (const float*)d_in[10];
    const float* be2  = (const float*)d_in[11];
    const float* m2   = (const float*)d_in[12];
    const float* v2   = (const float*)d_in[13];
    float* out = (float*)d_out;

    cudaFuncSetAttribute(mlp_kernel, cudaFuncAttributeMaxDynamicSharedMemorySize,
                         SMEM_BYTES);

    cudaStream_t s0 = (cudaStream_t)0;

    // fork side stream from s0
    cudaEventRecord(g_hx.eFork, s0);
    cudaStreamWaitEvent(g_hx.s2, g_hx.eFork, 0);

    xyzq_kernel<<<(Bv * Nv) / 256, 256, 0, s0>>>(xyz);                          // #1
    pack_kernel<<<dim3(Nv / 32, Bv), dim3(32, 16), 0, g_hx.s2>>>(xyz, feat);    // #2
    combo_kernel<<<58 + (Bv * Pv) / 16, 256, 0, g_hx.s2>>>(W1, W2, xyz, feat);  // #3
    cudaEventRecord(g_hx.eJoin, g_hx.s2);

    knn_kernel<<<(Bv * Pv) / 16, 256, 0, s0>>>();                               // #4 (ncu slot)
    cudaStreamWaitEvent(s0, g_hx.eJoin, 0);
    mlp_kernel<<<Bv * Pv / 16, 256, SMEM_BYTES, s0>>>(b1, g1, be1, m1, v1,
                                                      b2, g2, be2, m2, v2, out); // #5

    tail_kernel<<<256, 256, 0, g_hx.s2>>>(xyz, out);                            // #6
    cudaEventRecord(g_hx.eJoin2, g_hx.s2);
    cudaStreamWaitEvent(s0, g_hx.eJoin2, 0);
}